// round 4
// baseline (speedup 1.0000x reference)
#include <cuda_runtime.h>
#include <cuda_bf16.h>

// Two horizontally-adjacent patches per thread, packed f32x2 arithmetic.
// R4: force 8 blocks/SM (64 regs/thread) to lift occupancy 24 -> 32 warps/SM.
//
// Algebra (validated R1-R3, rel_err ~9e-7):
//  * encoding diagonal after H^4: a(s) = (1/4) e^{i Psi(s)}, Psi via CSE tree
//  * RX layer: 4 packed register butterflies
//  * CNOT ring folded into Walsh masks {7,12,14,15} on |a|^2 (partial FWHT)
//  * 1/16 scale folded into final outputs

typedef unsigned long long u64;

__device__ __forceinline__ u64 pk2(float lo, float hi) {
    u64 r; asm("mov.b64 %0,{%1,%2};" : "=l"(r) : "f"(lo), "f"(hi)); return r;
}
__device__ __forceinline__ void unpk(u64 v, float& lo, float& hi) {
    asm("mov.b64 {%0,%1},%2;" : "=f"(lo), "=f"(hi) : "l"(v));
}
__device__ __forceinline__ u64 add2(u64 a, u64 b) {
    u64 d; asm("add.rn.f32x2 %0,%1,%2;" : "=l"(d) : "l"(a), "l"(b)); return d;
}
__device__ __forceinline__ u64 sub2(u64 a, u64 b) {
    u64 d; asm("sub.rn.f32x2 %0,%1,%2;" : "=l"(d) : "l"(a), "l"(b)); return d;
}
__device__ __forceinline__ u64 mul2(u64 a, u64 b) {
    u64 d; asm("mul.rn.f32x2 %0,%1,%2;" : "=l"(d) : "l"(a), "l"(b)); return d;
}
__device__ __forceinline__ u64 fma2(u64 a, u64 b, u64 c) {
    u64 d; asm("fma.rn.f32x2 %0,%1,%2,%3;" : "=l"(d) : "l"(a), "l"(b), "l"(c)); return d;
}

__global__ void __launch_bounds__(128, 8)
qconv_kernel(const float* __restrict__ img,
             const float* __restrict__ wts,
             float* __restrict__ out,
             int npair)
{
    int tid = blockIdx.x * blockDim.x + threadIdx.x;
    if (tid >= npair) return;

    int b    = tid / 98;            // image
    int rem2 = tid - b * 98;        // j*7 + k2
    int j    = rem2 / 7;
    int k2   = rem2 - j * 7;

    const float4* rp = reinterpret_cast<const float4*>(
        img + (size_t)b * 784 + (size_t)(2 * j) * 28 + (size_t)(4 * k2));
    float4 q0 = rp[0];   // row 2j  : A.x0 A.x1 B.x0 B.x1
    float4 q1 = rp[7];   // row 2j+1: A.x2 A.x3 B.x2 B.x3

    u64 x0 = pk2(q0.x, q0.z);
    u64 x1 = pk2(q0.y, q0.w);
    u64 x2 = pk2(q1.x, q1.z);
    u64 x3 = pk2(q1.y, q1.w);

    const u64 HR2 = pk2(0.3925f, 0.3925f);   // 0.785/2
    u64 h0 = mul2(x0, HR2), h1 = mul2(x1, HR2);
    u64 h2 = mul2(x2, HR2), h3 = mul2(x3, HR2);
    u64 p01 = mul2(h0, x1), p02 = mul2(h0, x2), p03 = mul2(h0, x3);
    u64 p12 = mul2(h1, x2), p13 = mul2(h1, x3), p23 = mul2(h2, x3);

    // single-qubit phase bases
    u64 a01 = add2(h0, h1), b01 = sub2(h0, h1);
    u64 a23 = add2(h2, h3), b23 = sub2(h2, h3);
    u64 SA = add2(a01, a23), SB = sub2(a01, a23);
    u64 SC = add2(b01, a23), SD = sub2(b01, a23);
    u64 SE = add2(a01, b23), SF = sub2(a01, b23);
    u64 SG = add2(b01, b23), SH = sub2(b01, b23);

    // pair phase bases
    u64 m = add2(p12, p13), n = sub2(p12, p13);
    u64 t_pp = sub2(p01, m), t_mm = add2(p01, m);
    u64 t_pm = sub2(p01, n), t_mp = add2(p01, n);
    u64 u = add2(p02, p03), v = sub2(p02, p03);
    u64 q_pp = sub2(u, p23), q_mm = add2(u, p23);
    u64 q_pm = add2(v, p23), q_mp = sub2(v, p23);

    u64 P111  = add2(t_pp, q_pp);
    u64 P110  = add2(t_pm, q_pm);
    u64 P101  = sub2(t_mp, q_mp);
    u64 P100  = sub2(t_mm, q_mm);
    u64 P011  = sub2(q_pp, t_pp);
    u64 P010  = sub2(q_pm, t_pm);
    u64 Pn001 = add2(t_mp, q_mp);
    u64 Pn000 = add2(t_mm, q_mm);

    // Psi(s) = S(s) + P(g(s)); negatives expressed via operand order of sub2.
    u64 psi[16];
    psi[15] = sub2(SA, Pn000);
    psi[0]  = sub2(sub2(Pn000, Pn000), add2(SA, Pn000));  // -(SA+Pn000)
    // cheaper: -(SA+Pn000) = (0 - (SA+Pn000)); reuse a zero made once:
    // (kept simple below — compiler folds)
    psi[1]  = sub2(sub2(SE, SE), add2(SE, Pn001));        // -(SE+Pn001)
    psi[2]  = sub2(P010, SF);
    psi[3]  = sub2(P011, SB);
    psi[4]  = sub2(P100, SC);
    psi[5]  = sub2(P101, SG);
    psi[6]  = sub2(P110, SH);
    psi[7]  = sub2(P111, SD);
    psi[8]  = add2(SD, P111);
    psi[9]  = add2(SH, P110);
    psi[10] = add2(SG, P101);
    psi[11] = add2(SC, P100);
    psi[12] = add2(SB, P011);
    psi[13] = add2(SF, P010);
    psi[14] = sub2(SE, Pn001);

    // amplitudes (unscaled): per-lane sincos
    u64 AR[16], AI[16];
#pragma unroll
    for (int s = 0; s < 16; ++s) {
        float pa, pb, sa, ca, sb, cb;
        unpk(psi[s], pa, pb);
        __sincosf(pa, &sa, &ca);
        __sincosf(pb, &sb, &cb);
        AR[s] = pk2(ca, cb);
        AI[s] = pk2(sa, sb);
    }

    // RX(w_q) butterflies (uniform angles)
#pragma unroll
    for (int q = 0; q < 4; ++q) {
        float sw, cw;
        __sincosf(__ldg(wts + q) * 0.5f, &sw, &cw);
        u64 cw2 = pk2(cw, cw), sw2 = pk2(sw, sw);
        int bit = 1 << (3 - q);
#pragma unroll
        for (int s = 0; s < 16; ++s) {
            if (s & bit) continue;
            int t = s | bit;
            u64 a0r = AR[s], a0i = AI[s];
            u64 a1r = AR[t], a1i = AI[t];
            AR[s] = fma2(cw2, a0r, mul2(sw2, a1i));
            AI[s] = sub2(mul2(cw2, a0i), mul2(sw2, a1r));
            AR[t] = fma2(cw2, a1r, mul2(sw2, a0i));
            AI[t] = sub2(mul2(cw2, a1i), mul2(sw2, a0r));
        }
    }

    // probabilities
    u64 PZ[16];
#pragma unroll
    for (int s = 0; s < 16; ++s)
        PZ[s] = fma2(AI[s], AI[s], mul2(AR[s], AR[s]));

    // Walsh coefficients at masks 7, 12, 14, 15 (CNOT ring folded in)
    u64 d[8], sm[8];
#pragma unroll
    for (int i = 0; i < 8; ++i) {
        d[i]  = sub2(PZ[2 * i], PZ[2 * i + 1]);
        sm[i] = add2(PZ[2 * i], PZ[2 * i + 1]);
    }
    u64 dd[4], ss[4], sd[4];
#pragma unroll
    for (int i = 0; i < 4; ++i) {
        dd[i] = sub2(d[2 * i],  d[2 * i + 1]);
        ss[i] = add2(sm[2 * i], sm[2 * i + 1]);
        sd[i] = sub2(sm[2 * i], sm[2 * i + 1]);
    }
    u64 ddd0 = sub2(dd[0], dd[1]), ddd1 = sub2(dd[2], dd[3]);
    u64 ssd0 = sub2(ss[0], ss[1]), ssd1 = sub2(ss[2], ss[3]);
    u64 sdd0 = sub2(sd[0], sd[1]), sdd1 = sub2(sd[2], sd[3]);

    const u64 SC16 = pk2(0.0625f, 0.0625f);
    u64 ez0 = mul2(add2(ddd0, ddd1), SC16);   // mask 7  -> Z0
    u64 ez1 = mul2(sub2(ssd0, ssd1), SC16);   // mask 12 -> Z1
    u64 ez2 = mul2(sub2(sdd0, sdd1), SC16);   // mask 14 -> Z2
    u64 ez3 = mul2(sub2(ddd0, ddd1), SC16);   // mask 15 -> Z3

    // output (B,4,14,14), channels [Z3,Z2,Z1,Z0]; adjacent pair -> STG.64
    float* o = out + (size_t)b * 784 + (size_t)j * 14 + (size_t)(2 * k2);
    *reinterpret_cast<u64*>(o)       = ez3;
    *reinterpret_cast<u64*>(o + 196) = ez2;
    *reinterpret_cast<u64*>(o + 392) = ez1;
    *reinterpret_cast<u64*>(o + 588) = ez0;
}

extern "C" void kernel_launch(void* const* d_in, const int* in_sizes, int n_in,
                              void* d_out, int out_size) {
    const float* img = (const float*)d_in[0];
    const float* wts = (const float*)d_in[1];
    float* out = (float*)d_out;

    int B = in_sizes[0] / 784;
    int npair = B * 98;             // 14 * 7 patch-pairs per image

    int threads = 128;
    int blocks = (npair + threads - 1) / threads;
    qconv_kernel<<<blocks, threads>>>(img, wts, out, npair);
}